// round 13
// baseline (speedup 1.0000x reference)
#include <cuda_runtime.h>
#include <math.h>

#define B 16
#define T 8192
#define P 32
#define C 256
#define LMAX 8194
#define LOUT 8196

// ---------------- scratch (device globals; no runtime allocation) ----------
__device__ float g_h1[B * T * P];
__device__ float g_poses[B * T];
__device__ float g_pool[(size_t)B * LMAX * C];
__device__ int   g_maxbin;

// ---- packed f32x2 helpers -------------------------------------------------
__device__ __forceinline__ unsigned long long pk_dup(float a) {
    unsigned long long r;
    asm("mov.b64 %0, {%1, %1};" : "=l"(r) : "f"(a));
    return r;
}
__device__ __forceinline__ unsigned long long pk2(float lo, float hi) {
    unsigned long long r;
    asm("mov.b64 %0, {%1, %2};" : "=l"(r) : "f"(lo), "f"(hi));
    return r;
}
__device__ __forceinline__ void fma2(unsigned long long& acc,
                                     unsigned long long a, unsigned long long b) {
    asm("fma.rn.f32x2 %0, %1, %2, %0;" : "+l"(acc) : "l"(a), "l"(b));
}
__device__ __forceinline__ void unpk(unsigned long long a, float& lo, float& hi) {
    asm("mov.b64 {%0, %1}, %2;" : "=f"(lo), "=f"(hi) : "l"(a));
}

// ---- XLA-matching tanh (rational approximation, f32) ----------------------
__device__ __forceinline__ float xtanh(float x) {
    float cx = fminf(fmaxf(x, -7.90531110763549805f), 7.90531110763549805f);
    float x2 = cx * cx;
    float num = fmaf(x2, -2.76076847742355e-16f, 2.00018790482477e-13f);
    num = fmaf(num, x2, -8.60467152213735e-11f);
    num = fmaf(num, x2,  5.12229709037114e-08f);
    num = fmaf(num, x2,  1.48572235717979e-05f);
    num = fmaf(num, x2,  6.37261928875436e-04f);
    num = fmaf(num, x2,  4.89352455891786e-03f);
    num = num * cx;
    float den = fmaf(x2, 1.19825839466702e-06f, 1.18534705686654e-04f);
    den = fmaf(den, x2, 2.26843463243900e-03f);
    den = fmaf(den, x2, 4.89352518554385e-03f);
    float r = num / den;
    return (fabsf(x) < 4.0e-4f) ? x : r;
}
__device__ __forceinline__ float xsigmoid(float x) {
    return __fadd_rn(__fmul_rn(0.5f, xtanh(__fmul_rn(0.5f, x))), 0.5f);
}
// fast sigmoid: used ONLY where error does not feed the cumsum (GLU gate)
__device__ __forceinline__ float fsigmoid(float x) {
    return __fdividef(1.0f, 1.0f + __expf(-x));
}

// ---------------- zero the pool: bounded grid-stride over l < g_maxbin -----
#define ZBLK 1184
__global__ void k_zero_pool() {
    int mb = g_maxbin;
    size_t per = (size_t)mb * (C / 4);            // float4s per batch
    size_t stride = (size_t)gridDim.x * blockDim.x;
    size_t tid0 = (size_t)blockIdx.x * blockDim.x + threadIdx.x;
    float4 z = make_float4(0.f, 0.f, 0.f, 0.f);
#pragma unroll 1
    for (int b = 0; b < B; b++) {
        float4* dst = reinterpret_cast<float4*>(g_pool + (size_t)b * LMAX * C);
#pragma unroll 1
        for (size_t i = tid0; i < per; i += stride)
            dst[i] = z;
    }
}

// ---------------- predictor conv1: (2 -> 32, k=31) + BN + swish, f32x2 -----
__global__ void k_pred1(const float* __restrict__ x,
                        const float* __restrict__ p1w, const float* __restrict__ p1b,
                        const float* __restrict__ g, const float* __restrict__ bb,
                        const float* __restrict__ m, const float* __restrict__ v) {
    __shared__ float xs[94];
    __shared__ float xxs[94];
    __shared__ float wsp[2 * 31 * 32];
    int b = blockIdx.y;
    int t0 = blockIdx.x * 64;
    int tid = threadIdx.x;
    if (blockIdx.x == 0 && blockIdx.y == 0 && tid == 0) g_maxbin = 0;
    for (int idx = tid; idx < 2 * 31 * 32; idx += 256) {
        int hi = idx & 1; int op = (idx >> 1) & 15;
        int r = idx >> 5; int k = r % 31; int i = r / 31;
        wsp[idx] = p1w[((op + hi * 16) * 2 + i) * 31 + k];
    }
    for (int idx = tid; idx < 94; idx += 256) {
        int tt = t0 - 15 + idx;
        float xv = (tt >= 0 && tt < T) ? x[(size_t)b * T + tt] : 0.f;
        xs[idx] = xv;
        xxs[idx] = xv * xv;
    }
    __syncthreads();
    int op = tid & 15, slot = tid >> 4;
    int tb = slot * 4;
    const unsigned long long* wp = reinterpret_cast<const unsigned long long*>(wsp);
    unsigned long long acc2[4];
#pragma unroll
    for (int j = 0; j < 4; j++) acc2[j] = 0ull;
#pragma unroll
    for (int i = 0; i < 2; i++) {
        const float* src = i ? xxs : xs;
        float hw[34];
#pragma unroll
        for (int jj = 0; jj < 34; jj++) hw[jj] = src[tb + jj];
#pragma unroll
        for (int k = 0; k < 31; k++) {
            unsigned long long ww = wp[(i * 31 + k) * 16 + op];
#pragma unroll
            for (int j = 0; j < 4; j++) fma2(acc2[j], pk_dup(hw[k + j]), ww);
        }
    }
    int o0 = op, o1 = op + 16;
    float bias0 = p1b[o0], bias1 = p1b[o1];
    float s0 = g[o0] * (1.0f / sqrtf(v[o0] + 1e-5f));
    float s1 = g[o1] * (1.0f / sqrtf(v[o1] + 1e-5f));
    float off0 = __fsub_rn(bb[o0], __fmul_rn(m[o0], s0));
    float off1 = __fsub_rn(bb[o1], __fmul_rn(m[o1], s1));
#pragma unroll
    for (int j = 0; j < 4; j++) {
        float a0, a1;
        unpk(acc2[j], a0, a1);
        float u0 = __fadd_rn(__fmul_rn(__fadd_rn(a0, bias0), s0), off0);
        float u1 = __fadd_rn(__fmul_rn(__fadd_rn(a1, bias1), s1), off1);
        size_t base = ((size_t)b * T + t0 + tb + j) * P;
        g_h1[base + o0] = u0 * xsigmoid(u0);
        g_h1[base + o1] = u1 * xsigmoid(u1);
    }
}

// ---------------- fused conv2+BN+swish+conv3+sigmoid (pred2+pred3) ---------
#define HS 287   // hbuf row stride
__global__ void __launch_bounds__(256, 2)
k_pred23(const float* __restrict__ p2w, const float* __restrict__ p2b,
         const float* __restrict__ g, const float* __restrict__ bb,
         const float* __restrict__ m, const float* __restrict__ v,
         const float* __restrict__ p3w, const float* __restrict__ p3b,
         float* __restrict__ outw, float* __restrict__ outbm) {
    extern __shared__ float sm[];
    float* w2p  = sm;              // 15360 floats
    float* w3p  = sm + 15360;      // 960 floats
    float* hbuf = sm + 16320;      // 32 * 287 floats (holds h1, then h2)
    int b = blockIdx.y;
    int t0 = blockIdx.x * 256;
    int tid = threadIdx.x;
    for (int idx = tid; idx < 32 * 15 * 32; idx += 256) {
        int hi = idx & 1; int op = (idx >> 1) & 15;
        int r = idx >> 5; int k = r % 15; int i = r / 15;
        w2p[idx] = p2w[((op + hi * 16) * 32 + i) * 15 + k];
    }
    for (int idx = tid; idx < 960; idx += 256) {
        int o = idx & 1; int ik = idx >> 1;
        w3p[ik * 2 + o] = p3w[o * 480 + ik];
    }
    for (int idx = tid; idx < 32 * 284; idx += 256) {
        int i = idx & 31; int tt = idx >> 5;
        int t = t0 - 14 + tt;
        hbuf[i * HS + tt] = (t >= 0 && t < T) ? g_h1[((size_t)b * T + t) * P + i] : 0.f;
    }
    __syncthreads();
    int op = tid & 15, tg = tid >> 4;
    int tb = tg * 16;                    // hb base; hb -> t = t0 - 7 + hb
    unsigned long long acc2[16];
#pragma unroll
    for (int j = 0; j < 16; j++) acc2[j] = 0ull;
    unsigned long long accB = 0ull;      // tail h2: hb = 256 + tg (tg < 14)
#pragma unroll 1
    for (int i = 0; i < 32; i++) {
        unsigned long long hh[30];
#pragma unroll
        for (int j = 0; j < 30; j++) hh[j] = pk_dup(hbuf[i * HS + tb + j]);
        const unsigned long long* wrow =
            reinterpret_cast<const unsigned long long*>(w2p) + i * 15 * 16 + op;
#pragma unroll
        for (int k = 0; k < 15; k++) {
            unsigned long long ww = wrow[k * 16];
#pragma unroll
            for (int j = 0; j < 16; j++) fma2(acc2[j], hh[k + j], ww);
        }
        if (tg < 14) {
#pragma unroll
            for (int k = 0; k < 15; k++)
                fma2(accB, pk_dup(hbuf[i * HS + 256 + tg + k]), wrow[k * 16]);
        }
    }
    int o0 = op, o1 = op + 16;
    float bias0 = p2b[o0], bias1 = p2b[o1];
    float s0 = g[o0] * (1.0f / sqrtf(v[o0] + 1e-5f));
    float s1 = g[o1] * (1.0f / sqrtf(v[o1] + 1e-5f));
    float off0 = __fsub_rn(bb[o0], __fmul_rn(m[o0], s0));
    float off1 = __fsub_rn(bb[o1], __fmul_rn(m[o1], s1));
#pragma unroll
    for (int j = 0; j < 16; j++) {
        float a0, a1;
        unpk(acc2[j], a0, a1);
        float u0 = __fadd_rn(__fmul_rn(__fadd_rn(a0, bias0), s0), off0);
        float u1 = __fadd_rn(__fmul_rn(__fadd_rn(a1, bias1), s1), off1);
        acc2[j] = pk2(u0 * xsigmoid(u0), u1 * xsigmoid(u1));
    }
    float vB0 = 0.f, vB1 = 0.f;
    if (tg < 14) {
        float a0, a1;
        unpk(accB, a0, a1);
        float u0 = __fadd_rn(__fmul_rn(__fadd_rn(a0, bias0), s0), off0);
        float u1 = __fadd_rn(__fmul_rn(__fadd_rn(a1, bias1), s1), off1);
        vB0 = u0 * xsigmoid(u0);
        vB1 = u1 * xsigmoid(u1);
    }
    __syncthreads();                     // all h1 reads complete
#pragma unroll
    for (int j = 0; j < 16; j++) {
        int hb = tb + j;
        int t = t0 - 7 + hb;
        bool in = (t >= 0 && t < T);
        float v0, v1;
        unpk(acc2[j], v0, v1);
        hbuf[o0 * HS + hb] = in ? v0 : 0.f;
        hbuf[o1 * HS + hb] = in ? v1 : 0.f;
    }
    if (tg < 14) {
        int hb = 256 + tg;
        int t = t0 - 7 + hb;
        bool in = (t >= 0 && t < T);
        hbuf[o0 * HS + hb] = in ? vB0 : 0.f;
        hbuf[o1 * HS + hb] = in ? vB1 : 0.f;
    }
    __syncthreads();
    const unsigned long long* w3u = reinterpret_cast<const unsigned long long*>(w3p);
    unsigned long long acc = 0ull;
#pragma unroll 1
    for (int i = 0; i < 32; i++) {
#pragma unroll
        for (int k = 0; k < 15; k++)
            fma2(acc, pk_dup(hbuf[i * HS + tid + k]), w3u[i * 15 + k]);
    }
    float a0, a1;
    unpk(acc, a0, a1);
    a0 = __fadd_rn(a0, p3b[0]);
    a1 = __fadd_rn(a1, p3b[1]);
    outw[(size_t)b * T + t0 + tid]  = xsigmoid(a0);
    outbm[(size_t)b * T + t0 + tid] = xsigmoid(a1);
}

// ---------------- cumsum: exact replica of JAX associative_scan ------------
__global__ void k_scan(const float* __restrict__ bm, const float* __restrict__ nm,
                       float* __restrict__ lens) {
    extern __shared__ float s[];      // 2*T - 1 floats
    int b = blockIdx.x;
    int tid = threadIdx.x;            // 512 threads
    float nmv = nm[0];
    for (int i = tid; i < T; i += 512)
        s[i] = __fmul_rn(bm[(size_t)b * T + i], nmv);
    __syncthreads();
    for (int n = T; n > 1; n >>= 1) {
        int off = 2 * (T - n);
        int dst = 2 * (T - (n >> 1));
        for (int i = tid; i < (n >> 1); i += 512)
            s[dst + i] = __fadd_rn(s[off + 2 * i], s[off + 2 * i + 1]);
        __syncthreads();
    }
    for (int n = 2; n <= T; n <<= 1) {
        int off_l = 2 * (T - n);
        int off_u = 2 * (T - (n >> 1));
        for (int i = tid; i < n; i += 512) {
            float val;
            if (i == 0)       val = s[off_l];
            else if (i & 1)   val = s[off_u + (i >> 1)];
            else              val = __fadd_rn(s[off_u + (i >> 1) - 1], s[off_l + i]);
            s[off_l + i] = val;
        }
        __syncthreads();
    }
    for (int i = tid; i < T; i += 512)
        g_poses[(size_t)b * T + i] = s[i];
    if (tid == 0) {
        float ln = floorf(s[T - 1]) + 2.0f;
        lens[b] = ln;
        atomicMax(&g_maxbin, (int)ln);
    }
}

// ---------------- fused main conv + BN + GLU + CIF scatter (tile 128) ------
// rolling packed x-window: 16 regs per 8-t group -> 1/9 the LDS traffic
__global__ void k_scatter(const float* __restrict__ x, const float* __restrict__ cw,
                          const float* __restrict__ g, const float* __restrict__ bb,
                          const float* __restrict__ m, const float* __restrict__ v,
                          const float* __restrict__ wts) {
    __shared__ float xs[136];
    __shared__ float wtt[128];
    __shared__ float pss[128];
    int b = blockIdx.y;
    int t0 = blockIdx.x * 128;
    int tid = threadIdx.x;     // channel c
    if (tid < 136) {
        int t = t0 - 4 + tid;
        xs[tid] = (t >= 0 && t < T) ? x[(size_t)b * T + t] : 0.f;
    }
    if (tid < 128) {
        wtt[tid] = wts[(size_t)b * T + t0 + tid];
        pss[tid] = g_poses[(size_t)b * T + t0 + tid];
    }
    int c = tid;
    unsigned long long wag[9];
#pragma unroll
    for (int k = 0; k < 9; k++)
        wag[k] = pk2(cw[c * 9 + k], cw[(c + 256) * 9 + k]);
    float sa = g[c] * (1.0f / sqrtf(v[c] + 1e-3f));
    float ba = __fsub_rn(bb[c], __fmul_rn(m[c], sa));
    float sg = g[c + 256] * (1.0f / sqrtf(v[c + 256] + 1e-3f));
    float bg = __fsub_rn(bb[c + 256], __fmul_rn(m[c + 256], sg));
    __syncthreads();
    float* poolb = g_pool + (size_t)b * LMAX * C;
    float accL = 0.f, accH = 0.f;
    int curfl = -1;
#pragma unroll 1
    for (int gg8 = 0; gg8 < 128; gg8 += 8) {
        unsigned long long xw[16];
#pragma unroll
        for (int j = 0; j < 16; j++) xw[j] = pk_dup(xs[gg8 + j]);
#pragma unroll
        for (int u = 0; u < 8; u++) {
            int tl = gg8 + u;
            unsigned long long acc2 = 0ull;
#pragma unroll
            for (int k = 0; k < 9; k++)
                fma2(acc2, xw[u + k], wag[k]);
            float a, gg;
            unpk(acc2, a, gg);
            a  = __fadd_rn(__fmul_rn(a, sa), ba);
            gg = __fadd_rn(__fmul_rn(gg, sg), bg);
            float f = a * fsigmoid(gg) * wtt[tl];
            float pos = pss[tl];
            float fp = floorf(pos);
            float w2v = __fsub_rn(pos, fp);
            float w1v = __fsub_rn(1.f, w2v);
            int fl = (int)fp;
            if (fl != curfl) {                  // block-uniform branch
                if (curfl >= 0) {
                    atomicAdd(poolb + (size_t)curfl * C + c, accL);
                    if (fl == curfl + 1) {
                        accL = accH;
                    } else {
                        atomicAdd(poolb + (size_t)(curfl + 1) * C + c, accH);
                        accL = 0.f;
                    }
                }
                accH = 0.f;
                curfl = fl;
            }
            accL = fmaf(w1v, f, accL);
            accH = fmaf(w2v, f, accH);
        }
    }
    atomicAdd(poolb + (size_t)curfl * C + c, accL);
    atomicAdd(poolb + (size_t)(curfl + 1) * C + c, accH);
}

// ---------------- transpose [b][l][c] -> [b][c][l], float4 stores ----------
__global__ void k_transpose(float* __restrict__ out) {
    __shared__ float tile[32][33];
    int b = blockIdx.z;
    int l0 = blockIdx.x * 32, c0 = blockIdx.y * 32;
    int tid = threadIdx.y * 32 + threadIdx.x;
    int mb = g_maxbin;
    int wcc = tid >> 3, wl4 = (tid & 7) * 4;
    size_t obase = ((size_t)b * C + c0 + wcc) * (size_t)LOUT + l0 + wl4;
    bool wvalid = (l0 + wl4 + 3 < LOUT);
    if (l0 >= mb) {
        if (wvalid)
            *reinterpret_cast<float4*>(out + obase) = make_float4(0.f, 0.f, 0.f, 0.f);
        else {
            for (int j = 0; j < 4; j++)
                if (l0 + wl4 + j < LOUT) out[obase + j] = 0.f;
        }
        return;
    }
    int lx = threadIdx.x, cy = threadIdx.y;
#pragma unroll
    for (int r = 0; r < 32; r += 8) {
        int l = l0 + cy + r;
        float vv = 0.f;
        if (l < mb) vv = g_pool[((size_t)b * LMAX + l) * C + c0 + lx];
        tile[cy + r][lx] = vv;
    }
    __syncthreads();
    float4 o4;
    o4.x = tile[wl4 + 0][wcc];
    o4.y = tile[wl4 + 1][wcc];
    o4.z = tile[wl4 + 2][wcc];
    o4.w = tile[wl4 + 3][wcc];
    if (wvalid)
        *reinterpret_cast<float4*>(out + obase) = o4;
    else {
        float ov[4] = {o4.x, o4.y, o4.z, o4.w};
        for (int j = 0; j < 4; j++)
            if (l0 + wl4 + j < LOUT) out[obase + j] = ov[j];
    }
}

// ---------------- host launcher -------------------------------------------
extern "C" void kernel_launch(void* const* d_in, const int* in_sizes, int n_in,
                              void* d_out, int out_size) {
    const float* x   = (const float*)d_in[0];
    const float* cw  = (const float*)d_in[1];
    const float* bng = (const float*)d_in[2];
    const float* bnb = (const float*)d_in[3];
    const float* bnm = (const float*)d_in[4];
    const float* bnv = (const float*)d_in[5];
    const float* p1w = (const float*)d_in[6];
    const float* p1b = (const float*)d_in[7];
    const float* g1  = (const float*)d_in[8];
    const float* b1  = (const float*)d_in[9];
    const float* m1  = (const float*)d_in[10];
    const float* v1  = (const float*)d_in[11];
    const float* p2w = (const float*)d_in[12];
    const float* p2b = (const float*)d_in[13];
    const float* g2  = (const float*)d_in[14];
    const float* b2  = (const float*)d_in[15];
    const float* m2  = (const float*)d_in[16];
    const float* v2  = (const float*)d_in[17];
    const float* p3w = (const float*)d_in[18];
    const float* p3b = (const float*)d_in[19];
    const float* nm  = (const float*)d_in[20];

    float* out = (float*)d_out;
    float* xevs    = out;
    float* lens    = out + (size_t)B * C * LOUT;
    float* bmoves  = lens + B;
    float* weights = bmoves + (size_t)B * T;

    int smem23 = (16320 + 32 * HS) * sizeof(float);   // 102016 B
    cudaFuncSetAttribute(k_pred23, cudaFuncAttributeMaxDynamicSharedMemorySize, smem23);
    int smemScan = (2 * T - 1) * sizeof(float);       // 65532 B
    cudaFuncSetAttribute(k_scan, cudaFuncAttributeMaxDynamicSharedMemorySize, smemScan);

    k_pred1<<<dim3(T / 64, B), 256>>>(x, p1w, p1b, g1, b1, m1, v1);
    k_pred23<<<dim3(T / 256, B), 256, smem23>>>(p2w, p2b, g2, b2, m2, v2,
                                                p3w, p3b, weights, bmoves);
    k_scan<<<B, 512, smemScan>>>(bmoves, nm, lens);
    k_zero_pool<<<ZBLK, 256>>>();
    k_scatter<<<dim3(T / 128, B), 256>>>(x, cw, bng, bnb, bnm, bnv, weights);
    k_transpose<<<dim3((LOUT + 31) / 32, C / 32, B), dim3(32, 8)>>>(xevs);
}

// round 14
// speedup vs baseline: 1.5935x; 1.5935x over previous
#include <cuda_runtime.h>
#include <math.h>

#define B 16
#define T 8192
#define P 32
#define C 256
#define LMAX 8194
#define LOUT 8196

// ---------------- scratch (device globals; no runtime allocation) ----------
__device__ float g_h1[B * T * P];
__device__ float g_poses[B * T];
__device__ float g_pool[(size_t)B * LMAX * C];
__device__ int   g_maxbin;

// ---- packed f32x2 helpers -------------------------------------------------
__device__ __forceinline__ unsigned long long pk_dup(float a) {
    unsigned long long r;
    asm("mov.b64 %0, {%1, %1};" : "=l"(r) : "f"(a));
    return r;
}
__device__ __forceinline__ unsigned long long pk2(float lo, float hi) {
    unsigned long long r;
    asm("mov.b64 %0, {%1, %2};" : "=l"(r) : "f"(lo), "f"(hi));
    return r;
}
__device__ __forceinline__ void fma2(unsigned long long& acc,
                                     unsigned long long a, unsigned long long b) {
    asm("fma.rn.f32x2 %0, %1, %2, %0;" : "+l"(acc) : "l"(a), "l"(b));
}
__device__ __forceinline__ void unpk(unsigned long long a, float& lo, float& hi) {
    asm("mov.b64 {%0, %1}, %2;" : "=f"(lo), "=f"(hi) : "l"(a));
}

// ---- XLA-matching tanh (rational approximation, f32) ----------------------
__device__ __forceinline__ float xtanh(float x) {
    float cx = fminf(fmaxf(x, -7.90531110763549805f), 7.90531110763549805f);
    float x2 = cx * cx;
    float num = fmaf(x2, -2.76076847742355e-16f, 2.00018790482477e-13f);
    num = fmaf(num, x2, -8.60467152213735e-11f);
    num = fmaf(num, x2,  5.12229709037114e-08f);
    num = fmaf(num, x2,  1.48572235717979e-05f);
    num = fmaf(num, x2,  6.37261928875436e-04f);
    num = fmaf(num, x2,  4.89352455891786e-03f);
    num = num * cx;
    float den = fmaf(x2, 1.19825839466702e-06f, 1.18534705686654e-04f);
    den = fmaf(den, x2, 2.26843463243900e-03f);
    den = fmaf(den, x2, 4.89352518554385e-03f);
    float r = num / den;
    return (fabsf(x) < 4.0e-4f) ? x : r;
}
__device__ __forceinline__ float xsigmoid(float x) {
    return __fadd_rn(__fmul_rn(0.5f, xtanh(__fmul_rn(0.5f, x))), 0.5f);
}
// fast sigmoid: used ONLY where error does not feed the cumsum (GLU gate)
__device__ __forceinline__ float fsigmoid(float x) {
    return __fdividef(1.0f, 1.0f + __expf(-x));
}

// ---------------- zero the pool: bounded grid-stride over l < g_maxbin -----
#define ZBLK 1184
__global__ void k_zero_pool() {
    int mb = g_maxbin;
    size_t per = (size_t)mb * (C / 4);            // float4s per batch
    size_t stride = (size_t)gridDim.x * blockDim.x;
    size_t tid0 = (size_t)blockIdx.x * blockDim.x + threadIdx.x;
    float4 z = make_float4(0.f, 0.f, 0.f, 0.f);
#pragma unroll 1
    for (int b = 0; b < B; b++) {
        float4* dst = reinterpret_cast<float4*>(g_pool + (size_t)b * LMAX * C);
#pragma unroll 1
        for (size_t i = tid0; i < per; i += stride)
            dst[i] = z;
    }
}

// ---------------- predictor conv1: (2 -> 32, k=31) + BN + swish, f32x2 -----
__global__ void k_pred1(const float* __restrict__ x,
                        const float* __restrict__ p1w, const float* __restrict__ p1b,
                        const float* __restrict__ g, const float* __restrict__ bb,
                        const float* __restrict__ m, const float* __restrict__ v) {
    __shared__ float xs[94];
    __shared__ float xxs[94];
    __shared__ float wsp[2 * 31 * 32];
    int b = blockIdx.y;
    int t0 = blockIdx.x * 64;
    int tid = threadIdx.x;
    if (blockIdx.x == 0 && blockIdx.y == 0 && tid == 0) g_maxbin = 0;
    for (int idx = tid; idx < 2 * 31 * 32; idx += 256) {
        int hi = idx & 1; int op = (idx >> 1) & 15;
        int r = idx >> 5; int k = r % 31; int i = r / 31;
        wsp[idx] = p1w[((op + hi * 16) * 2 + i) * 31 + k];
    }
    for (int idx = tid; idx < 94; idx += 256) {
        int tt = t0 - 15 + idx;
        float xv = (tt >= 0 && tt < T) ? x[(size_t)b * T + tt] : 0.f;
        xs[idx] = xv;
        xxs[idx] = xv * xv;
    }
    __syncthreads();
    int op = tid & 15, slot = tid >> 4;
    int tb = slot * 4;
    const unsigned long long* wp = reinterpret_cast<const unsigned long long*>(wsp);
    unsigned long long acc2[4];
#pragma unroll
    for (int j = 0; j < 4; j++) acc2[j] = 0ull;
#pragma unroll
    for (int i = 0; i < 2; i++) {
        const float* src = i ? xxs : xs;
        float hw[34];
#pragma unroll
        for (int jj = 0; jj < 34; jj++) hw[jj] = src[tb + jj];
#pragma unroll
        for (int k = 0; k < 31; k++) {
            unsigned long long ww = wp[(i * 31 + k) * 16 + op];
#pragma unroll
            for (int j = 0; j < 4; j++) fma2(acc2[j], pk_dup(hw[k + j]), ww);
        }
    }
    int o0 = op, o1 = op + 16;
    float bias0 = p1b[o0], bias1 = p1b[o1];
    float s0 = g[o0] * (1.0f / sqrtf(v[o0] + 1e-5f));
    float s1 = g[o1] * (1.0f / sqrtf(v[o1] + 1e-5f));
    float off0 = __fsub_rn(bb[o0], __fmul_rn(m[o0], s0));
    float off1 = __fsub_rn(bb[o1], __fmul_rn(m[o1], s1));
#pragma unroll
    for (int j = 0; j < 4; j++) {
        float a0, a1;
        unpk(acc2[j], a0, a1);
        float u0 = __fadd_rn(__fmul_rn(__fadd_rn(a0, bias0), s0), off0);
        float u1 = __fadd_rn(__fmul_rn(__fadd_rn(a1, bias1), s1), off1);
        size_t base = ((size_t)b * T + t0 + tb + j) * P;
        g_h1[base + o0] = u0 * xsigmoid(u0);
        g_h1[base + o1] = u1 * xsigmoid(u1);
    }
}

// ---------------- fused conv2+BN+swish+conv3+sigmoid (pred2+pred3) ---------
#define HS 287   // hbuf row stride
__global__ void __launch_bounds__(256, 2)
k_pred23(const float* __restrict__ p2w, const float* __restrict__ p2b,
         const float* __restrict__ g, const float* __restrict__ bb,
         const float* __restrict__ m, const float* __restrict__ v,
         const float* __restrict__ p3w, const float* __restrict__ p3b,
         float* __restrict__ outw, float* __restrict__ outbm) {
    extern __shared__ float sm[];
    float* w2p  = sm;              // 15360 floats
    float* w3p  = sm + 15360;      // 960 floats
    float* hbuf = sm + 16320;      // 32 * 287 floats (holds h1, then h2)
    int b = blockIdx.y;
    int t0 = blockIdx.x * 256;
    int tid = threadIdx.x;
    for (int idx = tid; idx < 32 * 15 * 32; idx += 256) {
        int hi = idx & 1; int op = (idx >> 1) & 15;
        int r = idx >> 5; int k = r % 15; int i = r / 15;
        w2p[idx] = p2w[((op + hi * 16) * 32 + i) * 15 + k];
    }
    for (int idx = tid; idx < 960; idx += 256) {
        int o = idx & 1; int ik = idx >> 1;
        w3p[ik * 2 + o] = p3w[o * 480 + ik];
    }
    for (int idx = tid; idx < 32 * 284; idx += 256) {
        int i = idx & 31; int tt = idx >> 5;
        int t = t0 - 14 + tt;
        hbuf[i * HS + tt] = (t >= 0 && t < T) ? g_h1[((size_t)b * T + t) * P + i] : 0.f;
    }
    __syncthreads();
    int op = tid & 15, tg = tid >> 4;
    int tb = tg * 16;                    // hb base; hb -> t = t0 - 7 + hb
    unsigned long long acc2[16];
#pragma unroll
    for (int j = 0; j < 16; j++) acc2[j] = 0ull;
    unsigned long long accB = 0ull;      // tail h2: hb = 256 + tg (tg < 14)
#pragma unroll 1
    for (int i = 0; i < 32; i++) {
        unsigned long long hh[30];
#pragma unroll
        for (int j = 0; j < 30; j++) hh[j] = pk_dup(hbuf[i * HS + tb + j]);
        const unsigned long long* wrow =
            reinterpret_cast<const unsigned long long*>(w2p) + i * 15 * 16 + op;
#pragma unroll
        for (int k = 0; k < 15; k++) {
            unsigned long long ww = wrow[k * 16];
#pragma unroll
            for (int j = 0; j < 16; j++) fma2(acc2[j], hh[k + j], ww);
        }
        if (tg < 14) {
#pragma unroll
            for (int k = 0; k < 15; k++)
                fma2(accB, pk_dup(hbuf[i * HS + 256 + tg + k]), wrow[k * 16]);
        }
    }
    int o0 = op, o1 = op + 16;
    float bias0 = p2b[o0], bias1 = p2b[o1];
    float s0 = g[o0] * (1.0f / sqrtf(v[o0] + 1e-5f));
    float s1 = g[o1] * (1.0f / sqrtf(v[o1] + 1e-5f));
    float off0 = __fsub_rn(bb[o0], __fmul_rn(m[o0], s0));
    float off1 = __fsub_rn(bb[o1], __fmul_rn(m[o1], s1));
#pragma unroll
    for (int j = 0; j < 16; j++) {
        float a0, a1;
        unpk(acc2[j], a0, a1);
        float u0 = __fadd_rn(__fmul_rn(__fadd_rn(a0, bias0), s0), off0);
        float u1 = __fadd_rn(__fmul_rn(__fadd_rn(a1, bias1), s1), off1);
        acc2[j] = pk2(u0 * xsigmoid(u0), u1 * xsigmoid(u1));
    }
    float vB0 = 0.f, vB1 = 0.f;
    if (tg < 14) {
        float a0, a1;
        unpk(accB, a0, a1);
        float u0 = __fadd_rn(__fmul_rn(__fadd_rn(a0, bias0), s0), off0);
        float u1 = __fadd_rn(__fmul_rn(__fadd_rn(a1, bias1), s1), off1);
        vB0 = u0 * xsigmoid(u0);
        vB1 = u1 * xsigmoid(u1);
    }
    __syncthreads();                     // all h1 reads complete
#pragma unroll
    for (int j = 0; j < 16; j++) {
        int hb = tb + j;
        int t = t0 - 7 + hb;
        bool in = (t >= 0 && t < T);
        float v0, v1;
        unpk(acc2[j], v0, v1);
        hbuf[o0 * HS + hb] = in ? v0 : 0.f;
        hbuf[o1 * HS + hb] = in ? v1 : 0.f;
    }
    if (tg < 14) {
        int hb = 256 + tg;
        int t = t0 - 7 + hb;
        bool in = (t >= 0 && t < T);
        hbuf[o0 * HS + hb] = in ? vB0 : 0.f;
        hbuf[o1 * HS + hb] = in ? vB1 : 0.f;
    }
    __syncthreads();
    const unsigned long long* w3u = reinterpret_cast<const unsigned long long*>(w3p);
    unsigned long long acc = 0ull;
#pragma unroll 1
    for (int i = 0; i < 32; i++) {
#pragma unroll
        for (int k = 0; k < 15; k++)
            fma2(acc, pk_dup(hbuf[i * HS + tid + k]), w3u[i * 15 + k]);
    }
    float a0, a1;
    unpk(acc, a0, a1);
    a0 = __fadd_rn(a0, p3b[0]);
    a1 = __fadd_rn(a1, p3b[1]);
    outw[(size_t)b * T + t0 + tid]  = xsigmoid(a0);
    outbm[(size_t)b * T + t0 + tid] = xsigmoid(a1);
}

// ---------------- cumsum: exact replica of JAX associative_scan ------------
__global__ void k_scan(const float* __restrict__ bm, const float* __restrict__ nm,
                       float* __restrict__ lens) {
    extern __shared__ float s[];      // 2*T - 1 floats
    int b = blockIdx.x;
    int tid = threadIdx.x;            // 512 threads
    float nmv = nm[0];
    for (int i = tid; i < T; i += 512)
        s[i] = __fmul_rn(bm[(size_t)b * T + i], nmv);
    __syncthreads();
    for (int n = T; n > 1; n >>= 1) {
        int off = 2 * (T - n);
        int dst = 2 * (T - (n >> 1));
        for (int i = tid; i < (n >> 1); i += 512)
            s[dst + i] = __fadd_rn(s[off + 2 * i], s[off + 2 * i + 1]);
        __syncthreads();
    }
    for (int n = 2; n <= T; n <<= 1) {
        int off_l = 2 * (T - n);
        int off_u = 2 * (T - (n >> 1));
        for (int i = tid; i < n; i += 512) {
            float val;
            if (i == 0)       val = s[off_l];
            else if (i & 1)   val = s[off_u + (i >> 1)];
            else              val = __fadd_rn(s[off_u + (i >> 1) - 1], s[off_l + i]);
            s[off_l + i] = val;
        }
        __syncthreads();
    }
    for (int i = tid; i < T; i += 512)
        g_poses[(size_t)b * T + i] = s[i];
    if (tid == 0) {
        float ln = floorf(s[T - 1]) + 2.0f;
        lens[b] = ln;
        atomicMax(&g_maxbin, (int)ln);
    }
}

// ---------------- fused main conv + BN + GLU + CIF scatter (tile 128) ------
// float x-window: 16 regs per 8-t group; LDS per tl drops 9 -> 2
__global__ void k_scatter(const float* __restrict__ x, const float* __restrict__ cw,
                          const float* __restrict__ g, const float* __restrict__ bb,
                          const float* __restrict__ m, const float* __restrict__ v,
                          const float* __restrict__ wts) {
    __shared__ float xs[136];
    __shared__ float wtt[128];
    __shared__ float pss[128];
    int b = blockIdx.y;
    int t0 = blockIdx.x * 128;
    int tid = threadIdx.x;     // channel c
    if (tid < 136) {
        int t = t0 - 4 + tid;
        xs[tid] = (t >= 0 && t < T) ? x[(size_t)b * T + t] : 0.f;
    }
    if (tid < 128) {
        wtt[tid] = wts[(size_t)b * T + t0 + tid];
        pss[tid] = g_poses[(size_t)b * T + t0 + tid];
    }
    int c = tid;
    unsigned long long wag[9];
#pragma unroll
    for (int k = 0; k < 9; k++)
        wag[k] = pk2(cw[c * 9 + k], cw[(c + 256) * 9 + k]);
    float sa = g[c] * (1.0f / sqrtf(v[c] + 1e-3f));
    float ba = __fsub_rn(bb[c], __fmul_rn(m[c], sa));
    float sg = g[c + 256] * (1.0f / sqrtf(v[c + 256] + 1e-3f));
    float bg = __fsub_rn(bb[c + 256], __fmul_rn(m[c + 256], sg));
    __syncthreads();
    float* poolb = g_pool + (size_t)b * LMAX * C;
    float accL = 0.f, accH = 0.f;
    int curfl = -1;
#pragma unroll 1
    for (int gg8 = 0; gg8 < 128; gg8 += 8) {
        float xw[16];
#pragma unroll
        for (int j = 0; j < 16; j++) xw[j] = xs[gg8 + j];
#pragma unroll
        for (int u = 0; u < 8; u++) {
            int tl = gg8 + u;
            unsigned long long acc2 = 0ull;
#pragma unroll
            for (int k = 0; k < 9; k++)
                fma2(acc2, pk_dup(xw[u + k]), wag[k]);
            float a, gg;
            unpk(acc2, a, gg);
            a  = __fadd_rn(__fmul_rn(a, sa), ba);
            gg = __fadd_rn(__fmul_rn(gg, sg), bg);
            float f = a * fsigmoid(gg) * wtt[tl];
            float pos = pss[tl];
            float fp = floorf(pos);
            float w2v = __fsub_rn(pos, fp);
            float w1v = __fsub_rn(1.f, w2v);
            int fl = (int)fp;
            if (fl != curfl) {                  // block-uniform branch
                if (curfl >= 0) {
                    atomicAdd(poolb + (size_t)curfl * C + c, accL);
                    if (fl == curfl + 1) {
                        accL = accH;
                    } else {
                        atomicAdd(poolb + (size_t)(curfl + 1) * C + c, accH);
                        accL = 0.f;
                    }
                }
                accH = 0.f;
                curfl = fl;
            }
            accL = fmaf(w1v, f, accL);
            accH = fmaf(w2v, f, accH);
        }
    }
    atomicAdd(poolb + (size_t)curfl * C + c, accL);
    atomicAdd(poolb + (size_t)(curfl + 1) * C + c, accH);
}

// ---------------- transpose [b][l][c] -> [b][c][l], float4 stores ----------
__global__ void k_transpose(float* __restrict__ out) {
    __shared__ float tile[32][33];
    int b = blockIdx.z;
    int l0 = blockIdx.x * 32, c0 = blockIdx.y * 32;
    int tid = threadIdx.y * 32 + threadIdx.x;
    int mb = g_maxbin;
    int wcc = tid >> 3, wl4 = (tid & 7) * 4;
    size_t obase = ((size_t)b * C + c0 + wcc) * (size_t)LOUT + l0 + wl4;
    bool wvalid = (l0 + wl4 + 3 < LOUT);
    if (l0 >= mb) {
        if (wvalid)
            *reinterpret_cast<float4*>(out + obase) = make_float4(0.f, 0.f, 0.f, 0.f);
        else {
            for (int j = 0; j < 4; j++)
                if (l0 + wl4 + j < LOUT) out[obase + j] = 0.f;
        }
        return;
    }
    int lx = threadIdx.x, cy = threadIdx.y;
#pragma unroll
    for (int r = 0; r < 32; r += 8) {
        int l = l0 + cy + r;
        float vv = 0.f;
        if (l < mb) vv = g_pool[((size_t)b * LMAX + l) * C + c0 + lx];
        tile[cy + r][lx] = vv;
    }
    __syncthreads();
    float4 o4;
    o4.x = tile[wl4 + 0][wcc];
    o4.y = tile[wl4 + 1][wcc];
    o4.z = tile[wl4 + 2][wcc];
    o4.w = tile[wl4 + 3][wcc];
    if (wvalid)
        *reinterpret_cast<float4*>(out + obase) = o4;
    else {
        float ov[4] = {o4.x, o4.y, o4.z, o4.w};
        for (int j = 0; j < 4; j++)
            if (l0 + wl4 + j < LOUT) out[obase + j] = ov[j];
    }
}

// ---------------- host launcher -------------------------------------------
extern "C" void kernel_launch(void* const* d_in, const int* in_sizes, int n_in,
                              void* d_out, int out_size) {
    const float* x   = (const float*)d_in[0];
    const float* cw  = (const float*)d_in[1];
    const float* bng = (const float*)d_in[2];
    const float* bnb = (const float*)d_in[3];
    const float* bnm = (const float*)d_in[4];
    const float* bnv = (const float*)d_in[5];
    const float* p1w = (const float*)d_in[6];
    const float* p1b = (const float*)d_in[7];
    const float* g1  = (const float*)d_in[8];
    const float* b1  = (const float*)d_in[9];
    const float* m1  = (const float*)d_in[10];
    const float* v1  = (const float*)d_in[11];
    const float* p2w = (const float*)d_in[12];
    const float* p2b = (const float*)d_in[13];
    const float* g2  = (const float*)d_in[14];
    const float* b2  = (const float*)d_in[15];
    const float* m2  = (const float*)d_in[16];
    const float* v2  = (const float*)d_in[17];
    const float* p3w = (const float*)d_in[18];
    const float* p3b = (const float*)d_in[19];
    const float* nm  = (const float*)d_in[20];

    float* out = (float*)d_out;
    float* xevs    = out;
    float* lens    = out + (size_t)B * C * LOUT;
    float* bmoves  = lens + B;
    float* weights = bmoves + (size_t)B * T;

    int smem23 = (16320 + 32 * HS) * sizeof(float);   // 102016 B
    cudaFuncSetAttribute(k_pred23, cudaFuncAttributeMaxDynamicSharedMemorySize, smem23);
    int smemScan = (2 * T - 1) * sizeof(float);       // 65532 B
    cudaFuncSetAttribute(k_scan, cudaFuncAttributeMaxDynamicSharedMemorySize, smemScan);

    k_pred1<<<dim3(T / 64, B), 256>>>(x, p1w, p1b, g1, b1, m1, v1);
    k_pred23<<<dim3(T / 256, B), 256, smem23>>>(p2w, p2b, g2, b2, m2, v2,
                                                p3w, p3b, weights, bmoves);
    k_scan<<<B, 512, smemScan>>>(bmoves, nm, lens);
    k_zero_pool<<<ZBLK, 256>>>();
    k_scatter<<<dim3(T / 128, B), 256>>>(x, cw, bng, bnb, bnm, bnv, weights);
    k_transpose<<<dim3((LOUT + 31) / 32, C / 32, B), dim3(32, 8)>>>(xevs);
}

// round 17
// speedup vs baseline: 1.6074x; 1.0087x over previous
#include <cuda_runtime.h>
#include <math.h>

#define B 16
#define T 8192
#define P 32
#define C 256
#define LMAX 8194
#define LOUT 8196

// ---------------- scratch (device globals; no runtime allocation) ----------
__device__ float g_h1[B * T * P];
__device__ float g_poses[B * T];
__device__ float g_pool[(size_t)B * LMAX * C];
__device__ int   g_maxbin;

// ---- packed f32x2 helpers -------------------------------------------------
__device__ __forceinline__ unsigned long long pk_dup(float a) {
    unsigned long long r;
    asm("mov.b64 %0, {%1, %1};" : "=l"(r) : "f"(a));
    return r;
}
__device__ __forceinline__ unsigned long long pk2(float lo, float hi) {
    unsigned long long r;
    asm("mov.b64 %0, {%1, %2};" : "=l"(r) : "f"(lo), "f"(hi));
    return r;
}
__device__ __forceinline__ void fma2(unsigned long long& acc,
                                     unsigned long long a, unsigned long long b) {
    asm("fma.rn.f32x2 %0, %1, %2, %0;" : "+l"(acc) : "l"(a), "l"(b));
}
__device__ __forceinline__ void unpk(unsigned long long a, float& lo, float& hi) {
    asm("mov.b64 {%0, %1}, %2;" : "=f"(lo), "=f"(hi) : "l"(a));
}

// ---- XLA-matching tanh (rational approximation, f32) ----------------------
__device__ __forceinline__ float xtanh(float x) {
    float cx = fminf(fmaxf(x, -7.90531110763549805f), 7.90531110763549805f);
    float x2 = cx * cx;
    float num = fmaf(x2, -2.76076847742355e-16f, 2.00018790482477e-13f);
    num = fmaf(num, x2, -8.60467152213735e-11f);
    num = fmaf(num, x2,  5.12229709037114e-08f);
    num = fmaf(num, x2,  1.48572235717979e-05f);
    num = fmaf(num, x2,  6.37261928875436e-04f);
    num = fmaf(num, x2,  4.89352455891786e-03f);
    num = num * cx;
    float den = fmaf(x2, 1.19825839466702e-06f, 1.18534705686654e-04f);
    den = fmaf(den, x2, 2.26843463243900e-03f);
    den = fmaf(den, x2, 4.89352518554385e-03f);
    float r = num / den;
    return (fabsf(x) < 4.0e-4f) ? x : r;
}
__device__ __forceinline__ float xsigmoid(float x) {
    return __fadd_rn(__fmul_rn(0.5f, xtanh(__fmul_rn(0.5f, x))), 0.5f);
}
// fast sigmoid: used ONLY where error does not feed the cumsum (GLU gate)
__device__ __forceinline__ float fsigmoid(float x) {
    return __fdividef(1.0f, 1.0f + __expf(-x));
}

// ---------------- zero the pool: bounded grid-stride over l < g_maxbin -----
#define ZBLK 1184
__global__ void k_zero_pool() {
    int mb = g_maxbin;
    size_t per = (size_t)mb * (C / 4);            // float4s per batch
    size_t stride = (size_t)gridDim.x * blockDim.x;
    size_t tid0 = (size_t)blockIdx.x * blockDim.x + threadIdx.x;
    float4 z = make_float4(0.f, 0.f, 0.f, 0.f);
#pragma unroll 1
    for (int b = 0; b < B; b++) {
        float4* dst = reinterpret_cast<float4*>(g_pool + (size_t)b * LMAX * C);
#pragma unroll 1
        for (size_t i = tid0; i < per; i += stride)
            dst[i] = z;
    }
}

// ---------------- predictor conv1: (2 -> 32, k=31) + BN + swish, f32x2 -----
// tile 128 t; block 256 = 16 o-pairs x 16 slots; slot = 8 consecutive t
__global__ void k_pred1(const float* __restrict__ x,
                        const float* __restrict__ p1w, const float* __restrict__ p1b,
                        const float* __restrict__ g, const float* __restrict__ bb,
                        const float* __restrict__ m, const float* __restrict__ v) {
    __shared__ float xs[158];
    __shared__ float xxs[158];
    __shared__ float wsp[2 * 31 * 32];
    int b = blockIdx.y;
    int t0 = blockIdx.x * 128;
    int tid = threadIdx.x;
    if (blockIdx.x == 0 && blockIdx.y == 0 && tid == 0) g_maxbin = 0;
    for (int idx = tid; idx < 2 * 31 * 32; idx += 256) {
        int hi = idx & 1; int op = (idx >> 1) & 15;
        int r = idx >> 5; int k = r % 31; int i = r / 31;
        wsp[idx] = p1w[((op + hi * 16) * 2 + i) * 31 + k];
    }
    for (int idx = tid; idx < 158; idx += 256) {
        int tt = t0 - 15 + idx;
        float xv = (tt >= 0 && tt < T) ? x[(size_t)b * T + tt] : 0.f;
        xs[idx] = xv;
        xxs[idx] = xv * xv;
    }
    __syncthreads();
    int op = tid & 15, slot = tid >> 4;
    int tb = slot * 8;
    const unsigned long long* wp = reinterpret_cast<const unsigned long long*>(wsp);
    unsigned long long acc2[8];
#pragma unroll
    for (int j = 0; j < 8; j++) acc2[j] = 0ull;
#pragma unroll
    for (int i = 0; i < 2; i++) {
        const float* src = i ? xxs : xs;
        float hw[38];
#pragma unroll
        for (int jj = 0; jj < 38; jj++) hw[jj] = src[tb + jj];
#pragma unroll
        for (int k = 0; k < 31; k++) {
            unsigned long long ww = wp[(i * 31 + k) * 16 + op];
#pragma unroll
            for (int j = 0; j < 8; j++) fma2(acc2[j], pk_dup(hw[k + j]), ww);
        }
    }
    int o0 = op, o1 = op + 16;
    float bias0 = p1b[o0], bias1 = p1b[o1];
    float s0 = g[o0] * (1.0f / sqrtf(v[o0] + 1e-5f));
    float s1 = g[o1] * (1.0f / sqrtf(v[o1] + 1e-5f));
    float off0 = __fsub_rn(bb[o0], __fmul_rn(m[o0], s0));
    float off1 = __fsub_rn(bb[o1], __fmul_rn(m[o1], s1));
#pragma unroll
    for (int j = 0; j < 8; j++) {
        float a0, a1;
        unpk(acc2[j], a0, a1);
        float u0 = __fadd_rn(__fmul_rn(__fadd_rn(a0, bias0), s0), off0);
        float u1 = __fadd_rn(__fmul_rn(__fadd_rn(a1, bias1), s1), off1);
        size_t base = ((size_t)b * T + t0 + tb + j) * P;
        g_h1[base + o0] = u0 * xsigmoid(u0);
        g_h1[base + o1] = u1 * xsigmoid(u1);
    }
}

// ---------------- fused conv2+BN+swish+conv3+sigmoid (pred2+pred3) ---------
#define HS 287   // hbuf row stride
__global__ void __launch_bounds__(256, 2)
k_pred23(const float* __restrict__ p2w, const float* __restrict__ p2b,
         const float* __restrict__ g, const float* __restrict__ bb,
         const float* __restrict__ m, const float* __restrict__ v,
         const float* __restrict__ p3w, const float* __restrict__ p3b,
         float* __restrict__ outw, float* __restrict__ outbm) {
    extern __shared__ float sm[];
    float* w2p  = sm;              // 15360 floats
    float* w3p  = sm + 15360;      // 960 floats
    float* hbuf = sm + 16320;      // 32 * 287 floats (holds h1, then h2)
    int b = blockIdx.y;
    int t0 = blockIdx.x * 256;
    int tid = threadIdx.x;
    for (int idx = tid; idx < 32 * 15 * 32; idx += 256) {
        int hi = idx & 1; int op = (idx >> 1) & 15;
        int r = idx >> 5; int k = r % 15; int i = r / 15;
        w2p[idx] = p2w[((op + hi * 16) * 32 + i) * 15 + k];
    }
    for (int idx = tid; idx < 960; idx += 256) {
        int o = idx & 1; int ik = idx >> 1;
        w3p[ik * 2 + o] = p3w[o * 480 + ik];
    }
    for (int idx = tid; idx < 32 * 284; idx += 256) {
        int i = idx & 31; int tt = idx >> 5;
        int t = t0 - 14 + tt;
        hbuf[i * HS + tt] = (t >= 0 && t < T) ? g_h1[((size_t)b * T + t) * P + i] : 0.f;
    }
    __syncthreads();
    int op = tid & 15, tg = tid >> 4;
    int tb = tg * 16;                    // hb base; hb -> t = t0 - 7 + hb
    unsigned long long acc2[16];
#pragma unroll
    for (int j = 0; j < 16; j++) acc2[j] = 0ull;
    unsigned long long accB = 0ull;      // tail h2: hb = 256 + tg (tg < 14)
#pragma unroll 1
    for (int i = 0; i < 32; i++) {
        unsigned long long hh[30];
#pragma unroll
        for (int j = 0; j < 30; j++) hh[j] = pk_dup(hbuf[i * HS + tb + j]);
        const unsigned long long* wrow =
            reinterpret_cast<const unsigned long long*>(w2p) + i * 15 * 16 + op;
#pragma unroll
        for (int k = 0; k < 15; k++) {
            unsigned long long ww = wrow[k * 16];
#pragma unroll
            for (int j = 0; j < 16; j++) fma2(acc2[j], hh[k + j], ww);
        }
        if (tg < 14) {
#pragma unroll
            for (int k = 0; k < 15; k++)
                fma2(accB, pk_dup(hbuf[i * HS + 256 + tg + k]), wrow[k * 16]);
        }
    }
    int o0 = op, o1 = op + 16;
    float bias0 = p2b[o0], bias1 = p2b[o1];
    float s0 = g[o0] * (1.0f / sqrtf(v[o0] + 1e-5f));
    float s1 = g[o1] * (1.0f / sqrtf(v[o1] + 1e-5f));
    float off0 = __fsub_rn(bb[o0], __fmul_rn(m[o0], s0));
    float off1 = __fsub_rn(bb[o1], __fmul_rn(m[o1], s1));
#pragma unroll
    for (int j = 0; j < 16; j++) {
        float a0, a1;
        unpk(acc2[j], a0, a1);
        float u0 = __fadd_rn(__fmul_rn(__fadd_rn(a0, bias0), s0), off0);
        float u1 = __fadd_rn(__fmul_rn(__fadd_rn(a1, bias1), s1), off1);
        acc2[j] = pk2(u0 * xsigmoid(u0), u1 * xsigmoid(u1));
    }
    float vB0 = 0.f, vB1 = 0.f;
    if (tg < 14) {
        float a0, a1;
        unpk(accB, a0, a1);
        float u0 = __fadd_rn(__fmul_rn(__fadd_rn(a0, bias0), s0), off0);
        float u1 = __fadd_rn(__fmul_rn(__fadd_rn(a1, bias1), s1), off1);
        vB0 = u0 * xsigmoid(u0);
        vB1 = u1 * xsigmoid(u1);
    }
    __syncthreads();                     // all h1 reads complete
#pragma unroll
    for (int j = 0; j < 16; j++) {
        int hb = tb + j;
        int t = t0 - 7 + hb;
        bool in = (t >= 0 && t < T);
        float v0, v1;
        unpk(acc2[j], v0, v1);
        hbuf[o0 * HS + hb] = in ? v0 : 0.f;
        hbuf[o1 * HS + hb] = in ? v1 : 0.f;
    }
    if (tg < 14) {
        int hb = 256 + tg;
        int t = t0 - 7 + hb;
        bool in = (t >= 0 && t < T);
        hbuf[o0 * HS + hb] = in ? vB0 : 0.f;
        hbuf[o1 * HS + hb] = in ? vB1 : 0.f;
    }
    __syncthreads();
    const unsigned long long* w3u = reinterpret_cast<const unsigned long long*>(w3p);
    unsigned long long acc = 0ull;
#pragma unroll 1
    for (int i = 0; i < 32; i++) {
#pragma unroll
        for (int k = 0; k < 15; k++)
            fma2(acc, pk_dup(hbuf[i * HS + tid + k]), w3u[i * 15 + k]);
    }
    float a0, a1;
    unpk(acc, a0, a1);
    a0 = __fadd_rn(a0, p3b[0]);
    a1 = __fadd_rn(a1, p3b[1]);
    outw[(size_t)b * T + t0 + tid]  = xsigmoid(a0);
    outbm[(size_t)b * T + t0 + tid] = xsigmoid(a1);
}

// ---------------- cumsum: exact replica of JAX associative_scan ------------
__global__ void k_scan(const float* __restrict__ bm, const float* __restrict__ nm,
                       float* __restrict__ lens) {
    extern __shared__ float s[];      // 2*T - 1 floats
    int b = blockIdx.x;
    int tid = threadIdx.x;            // 1024 threads
    float nmv = nm[0];
    for (int i = tid; i < T; i += 1024)
        s[i] = __fmul_rn(bm[(size_t)b * T + i], nmv);
    __syncthreads();
    for (int n = T; n > 1; n >>= 1) {
        int off = 2 * (T - n);
        int dst = 2 * (T - (n >> 1));
        for (int i = tid; i < (n >> 1); i += 1024)
            s[dst + i] = __fadd_rn(s[off + 2 * i], s[off + 2 * i + 1]);
        __syncthreads();
    }
    for (int n = 2; n <= T; n <<= 1) {
        int off_l = 2 * (T - n);
        int off_u = 2 * (T - (n >> 1));
        for (int i = tid; i < n; i += 1024) {
            float val;
            if (i == 0)       val = s[off_l];
            else if (i & 1)   val = s[off_u + (i >> 1)];
            else              val = __fadd_rn(s[off_u + (i >> 1) - 1], s[off_l + i]);
            s[off_l + i] = val;
        }
        __syncthreads();
    }
    for (int i = tid; i < T; i += 1024)
        g_poses[(size_t)b * T + i] = s[i];
    if (tid == 0) {
        float ln = floorf(s[T - 1]) + 2.0f;
        lens[b] = ln;
        atomicMax(&g_maxbin, (int)ln);
    }
}

// ---------------- fused main conv + BN + GLU + CIF scatter (tile 128) ------
// float x-window: 16 regs per 8-t group; LDS per tl drops 9 -> 2
__global__ void k_scatter(const float* __restrict__ x, const float* __restrict__ cw,
                          const float* __restrict__ g, const float* __restrict__ bb,
                          const float* __restrict__ m, const float* __restrict__ v,
                          const float* __restrict__ wts) {
    __shared__ float xs[136];
    __shared__ float wtt[128];
    __shared__ float pss[128];
    int b = blockIdx.y;
    int t0 = blockIdx.x * 128;
    int tid = threadIdx.x;     // channel c
    if (tid < 136) {
        int t = t0 - 4 + tid;
        xs[tid] = (t >= 0 && t < T) ? x[(size_t)b * T + t] : 0.f;
    }
    if (tid < 128) {
        wtt[tid] = wts[(size_t)b * T + t0 + tid];
        pss[tid] = g_poses[(size_t)b * T + t0 + tid];
    }
    int c = tid;
    unsigned long long wag[9];
#pragma unroll
    for (int k = 0; k < 9; k++)
        wag[k] = pk2(cw[c * 9 + k], cw[(c + 256) * 9 + k]);
    float sa = g[c] * (1.0f / sqrtf(v[c] + 1e-3f));
    float ba = __fsub_rn(bb[c], __fmul_rn(m[c], sa));
    float sg = g[c + 256] * (1.0f / sqrtf(v[c + 256] + 1e-3f));
    float bg = __fsub_rn(bb[c + 256], __fmul_rn(m[c + 256], sg));
    __syncthreads();
    float* poolb = g_pool + (size_t)b * LMAX * C;
    float accL = 0.f, accH = 0.f;
    int curfl = -1;
#pragma unroll 1
    for (int gg8 = 0; gg8 < 128; gg8 += 8) {
        float xw[16];
#pragma unroll
        for (int j = 0; j < 16; j++) xw[j] = xs[gg8 + j];
#pragma unroll
        for (int u = 0; u < 8; u++) {
            int tl = gg8 + u;
            unsigned long long acc2 = 0ull;
#pragma unroll
            for (int k = 0; k < 9; k++)
                fma2(acc2, pk_dup(xw[u + k]), wag[k]);
            float a, gg;
            unpk(acc2, a, gg);
            a  = __fadd_rn(__fmul_rn(a, sa), ba);
            gg = __fadd_rn(__fmul_rn(gg, sg), bg);
            float f = a * fsigmoid(gg) * wtt[tl];
            float pos = pss[tl];
            float fp = floorf(pos);
            float w2v = __fsub_rn(pos, fp);
            float w1v = __fsub_rn(1.f, w2v);
            int fl = (int)fp;
            if (fl != curfl) {                  // block-uniform branch
                if (curfl >= 0) {
                    atomicAdd(poolb + (size_t)curfl * C + c, accL);
                    if (fl == curfl + 1) {
                        accL = accH;
                    } else {
                        atomicAdd(poolb + (size_t)(curfl + 1) * C + c, accH);
                        accL = 0.f;
                    }
                }
                accH = 0.f;
                curfl = fl;
            }
            accL = fmaf(w1v, f, accL);
            accH = fmaf(w2v, f, accH);
        }
    }
    atomicAdd(poolb + (size_t)curfl * C + c, accL);
    atomicAdd(poolb + (size_t)(curfl + 1) * C + c, accH);
}

// ---------------- transpose [b][l][c] -> [b][c][l], 128-l tiles, float4 ----
__global__ void k_transpose(float* __restrict__ out) {
    __shared__ float tile[128][33];
    int b = blockIdx.z;
    int l0 = blockIdx.x * 128, c0 = blockIdx.y * 32;
    int tid = threadIdx.y * 32 + threadIdx.x;
    int mb = g_maxbin;
    int wcc = tid >> 3, wl = (tid & 7) * 4;
    if (l0 >= mb) {    // untouched bins: pure zero output
#pragma unroll
        for (int s = 0; s < 4; s++) {
            int lb = l0 + s * 32 + wl;
            size_t obase = ((size_t)b * C + c0 + wcc) * (size_t)LOUT + lb;
            if (lb + 3 < LOUT)
                *reinterpret_cast<float4*>(out + obase) = make_float4(0.f, 0.f, 0.f, 0.f);
            else
                for (int j = 0; j < 4; j++)
                    if (lb + j < LOUT) out[obase + j] = 0.f;
        }
        return;
    }
    int lx = threadIdx.x, cy = threadIdx.y;
#pragma unroll
    for (int r = 0; r < 128; r += 8) {
        int l = l0 + cy + r;
        float vv = 0.f;
        if (l < mb && l < LMAX) vv = g_pool[((size_t)b * LMAX + l) * C + c0 + lx];
        tile[cy + r][lx] = vv;
    }
    __syncthreads();
#pragma unroll
    for (int s = 0; s < 4; s++) {
        int lb = l0 + s * 32 + wl;
        size_t obase = ((size_t)b * C + c0 + wcc) * (size_t)LOUT + lb;
        float4 o4;
        o4.x = tile[s * 32 + wl + 0][wcc];
        o4.y = tile[s * 32 + wl + 1][wcc];
        o4.z = tile[s * 32 + wl + 2][wcc];
        o4.w = tile[s * 32 + wl + 3][wcc];
        if (lb + 3 < LOUT)
            *reinterpret_cast<float4*>(out + obase) = o4;
        else {
            float ov[4] = {o4.x, o4.y, o4.z, o4.w};
            for (int j = 0; j < 4; j++)
                if (lb + j < LOUT) out[obase + j] = ov[j];
        }
    }
}

// ---------------- host launcher -------------------------------------------
extern "C" void kernel_launch(void* const* d_in, const int* in_sizes, int n_in,
                              void* d_out, int out_size) {
    const float* x   = (const float*)d_in[0];
    const float* cw  = (const float*)d_in[1];
    const float* bng = (const float*)d_in[2];
    const float* bnb = (const float*)d_in[3];
    const float* bnm = (const float*)d_in[4];
    const float* bnv = (const float*)d_in[5];
    const float* p1w = (const float*)d_in[6];
    const float* p1b = (const float*)d_in[7];
    const float* g1  = (const float*)d_in[8];
    const float* b1  = (const float*)d_in[9];
    const float* m1  = (const float*)d_in[10];
    const float* v1  = (const float*)d_in[11];
    const float* p2w = (const float*)d_in[12];
    const float* p2b = (const float*)d_in[13];
    const float* g2  = (const float*)d_in[14];
    const float* b2  = (const float*)d_in[15];
    const float* m2  = (const float*)d_in[16];
    const float* v2  = (const float*)d_in[17];
    const float* p3w = (const float*)d_in[18];
    const float* p3b = (const float*)d_in[19];
    const float* nm  = (const float*)d_in[20];

    float* out = (float*)d_out;
    float* xevs    = out;
    float* lens    = out + (size_t)B * C * LOUT;
    float* bmoves  = lens + B;
    float* weights = bmoves + (size_t)B * T;

    int smem23 = (16320 + 32 * HS) * sizeof(float);   // 102016 B
    cudaFuncSetAttribute(k_pred23, cudaFuncAttributeMaxDynamicSharedMemorySize, smem23);
    int smemScan = (2 * T - 1) * sizeof(float);       // 65532 B
    cudaFuncSetAttribute(k_scan, cudaFuncAttributeMaxDynamicSharedMemorySize, smemScan);

    k_pred1<<<dim3(T / 128, B), 256>>>(x, p1w, p1b, g1, b1, m1, v1);
    k_pred23<<<dim3(T / 256, B), 256, smem23>>>(p2w, p2b, g2, b2, m2, v2,
                                                p3w, p3b, weights, bmoves);
    k_scan<<<B, 1024, smemScan>>>(bmoves, nm, lens);
    k_zero_pool<<<ZBLK, 256>>>();
    k_scatter<<<dim3(T / 128, B), 256>>>(x, cw, bng, bnb, bnm, bnv, weights);
    k_transpose<<<dim3((LOUT + 127) / 128, C / 32, B), dim3(32, 8)>>>(xevs);
}